// round 1
// baseline (speedup 1.0000x reference)
#include <cuda_runtime.h>
#include <math.h>

// Problem dims (fixed by the dataset)
#define NN  5      // number of x slices / convs
#define BB  8      // batch
#define CC  256    // channels
#define HWD 1024   // H*W
#define KB  16     // K-chunk
#define TO  64     // o-tile (output-channel rows)
#define TP  64     // pixel tile (within one b, along hw)

// Scratch for preprocessed weights: M = W1+W2 (applied to x_j), W2 contiguous.
__device__ float g_M [NN * CC * CC];
__device__ float g_W2[NN * CC * CC];

__global__ void prep_kernel(const float* __restrict__ w) {
    int idx = blockIdx.x * blockDim.x + threadIdx.x;   // over NN*CC*CC
    if (idx >= NN * CC * CC) return;
    int c  = idx & (CC - 1);
    int oi = idx >> 8;                                  // i*CC + o
    const float* row = w + (size_t)oi * (2 * CC);
    float w2 = row[CC + c];
    g_W2[idx] = w2;
    g_M[idx]  = row[c] + w2;
}

// One CTA: fixed i, 64 o-rows, 64 pixels (one b, hw range).
// Computes v_j = M_i @ x_j for j=0..4 and u = W2_i @ x_i (+bias),
// then the fused edge/softmax/aggregate epilogue. No intermediates to GMEM.
__global__ __launch_bounds__(256, 1) void fused_kernel(
    const float* __restrict__ x,
    const float* __restrict__ bias,
    float* __restrict__ out)
{
    __shared__ float Ms[TO][KB + 4];           // A tile for M_i   (pad to 20 floats/row)
    __shared__ float Ws[TO][KB + 4];           // A tile for W2_i
    __shared__ float Xs[NN][KB][TP];           // B tiles for all 5 x_j

    const int i   = blockIdx.z;
    const int o0  = blockIdx.y * TO;
    const int b   = blockIdx.x >> 4;           // 16 hw-tiles per b
    const int hw0 = (blockIdx.x & 15) * TP;

    const int tid = threadIdx.x;
    const int tx  = tid & 15;                  // pixel sub-tile  (4 cols each)
    const int ty  = tid >> 4;                  // o sub-tile      (4 rows each)

    float accV[NN][4][4];
    float accU[4][4];
    #pragma unroll
    for (int j = 0; j < NN; j++)
        #pragma unroll
        for (int r = 0; r < 4; r++)
            #pragma unroll
            for (int c = 0; c < 4; c++) accV[j][r][c] = 0.f;
    #pragma unroll
    for (int r = 0; r < 4; r++)
        #pragma unroll
        for (int c = 0; c < 4; c++) accU[r][c] = 0.f;

    const float* Mi = g_M  + ((size_t)i * CC + o0) * CC;
    const float* Wi = g_W2 + ((size_t)i * CC + o0) * CC;

    for (int k0 = 0; k0 < CC; k0 += KB) {
        __syncthreads();
        // --- load A tiles: 64 rows x 16 k = 256 float4 each; 1 per thread ---
        {
            int k4 = tid & 3;
            int o  = tid >> 2;
            const float4 mv = *(const float4*)(Mi + (size_t)o * CC + k0 + k4 * 4);
            *(float4*)&Ms[o][k4 * 4] = mv;
            const float4 wv = *(const float4*)(Wi + (size_t)o * CC + k0 + k4 * 4);
            *(float4*)&Ws[o][k4 * 4] = wv;
        }
        // --- load B tiles: 5 * 16k * 16 float4 = 1280 float4; 5 per thread ---
        #pragma unroll
        for (int t = 0; t < 5; t++) {
            int idx = tid + t * 256;
            int p4  = idx & 15;
            int k   = (idx >> 4) & (KB - 1);
            int j   = idx >> 8;
            const float4 xv = *(const float4*)(
                x + ((((size_t)j * BB + b) * CC + k0 + k) * HWD) + hw0 + p4 * 4);
            *(float4*)&Xs[j][k][p4 * 4] = xv;
        }
        __syncthreads();

        // --- 6 simultaneous rank-KB updates ---
        #pragma unroll
        for (int k = 0; k < KB; k++) {
            float aM[4], aW[4];
            #pragma unroll
            for (int r = 0; r < 4; r++) {
                aM[r] = Ms[ty * 4 + r][k];
                aW[r] = Ws[ty * 4 + r][k];
            }
            float bx[NN][4];
            #pragma unroll
            for (int j = 0; j < NN; j++) {
                float4 q = *(const float4*)&Xs[j][k][tx * 4];
                bx[j][0] = q.x; bx[j][1] = q.y; bx[j][2] = q.z; bx[j][3] = q.w;
            }
            #pragma unroll
            for (int j = 0; j < NN; j++) {
                #pragma unroll
                for (int r = 0; r < 4; r++)
                    #pragma unroll
                    for (int c = 0; c < 4; c++)
                        accV[j][r][c] = fmaf(aM[r], bx[j][c], accV[j][r][c]);
                if (j == i) {   // u = W2_i @ x_i reuses the x_i B-tile
                    #pragma unroll
                    for (int r = 0; r < 4; r++)
                        #pragma unroll
                        for (int c = 0; c < 4; c++)
                            accU[r][c] = fmaf(aW[r], bx[j][c], accU[r][c]);
                }
            }
        }
    }

    // --- fused epilogue: t = v_j + u + b; e = |x_j - t| thresholded; softmax_j; sum ---
    #pragma unroll
    for (int r = 0; r < 4; r++) {
        const int o  = o0 + ty * 4 + r;
        const float bv = bias[i * CC + o];
        float xr[NN][4];
        #pragma unroll
        for (int j = 0; j < NN; j++) {
            float4 q = *(const float4*)(
                x + ((((size_t)j * BB + b) * CC + o) * HWD) + hw0 + tx * 4);
            xr[j][0] = q.x; xr[j][1] = q.y; xr[j][2] = q.z; xr[j][3] = q.w;
        }
        float resv[4];
        #pragma unroll
        for (int c = 0; c < 4; c++) {
            const float u = accU[r][c] + bv;
            float e[NN];
            float m = 0.f;                       // all e >= 0, so max >= 0
            #pragma unroll
            for (int j = 0; j < NN; j++) {
                float t = accV[j][r][c] + u;
                float d = fabsf(xr[j][c] - t);
                e[j] = (d > 0.3f) ? d : 0.f;
                m = fmaxf(m, e[j]);
            }
            float s = 0.f, a = 0.f;
            #pragma unroll
            for (int j = 0; j < NN; j++) {
                float wgt = __expf(e[j] - m);
                s += wgt;
                a = fmaf(wgt, xr[j][c], a);
            }
            resv[c] = a / s;
        }
        *(float4*)(out + ((((size_t)i * BB + b) * CC + o) * HWD) + hw0 + tx * 4) =
            make_float4(resv[0], resv[1], resv[2], resv[3]);
    }
}

extern "C" void kernel_launch(void* const* d_in, const int* in_sizes, int n_in,
                              void* d_out, int out_size) {
    const float* x    = (const float*)d_in[0];   // [5,8,256,32,32]
    const float* w    = (const float*)d_in[1];   // [5,256,512]
    const float* bias = (const float*)d_in[2];   // [5,256]
    float* out = (float*)d_out;                  // [5,8,256,32,32]

    prep_kernel<<<(NN * CC * CC + 255) / 256, 256>>>(w);
    // grid: x = b(8) * hw_tiles(16) = 128, y = o_tiles(4), z = i(5)
    fused_kernel<<<dim3(128, 4, 5), 256>>>(x, bias, out);
}

// round 2
// speedup vs baseline: 1.2203x; 1.2203x over previous
#include <cuda_runtime.h>
#include <math.h>

// Problem dims (fixed by the dataset)
#define NN  5      // number of x slices / convs
#define BB  8      // batch
#define CC  256    // channels
#define HWD 1024   // H*W
#define KB  16     // K-chunk
#define TO  64     // o-tile (output-channel rows)
#define TP  64     // pixel tile (within one b, along hw)

// Packed fp32x2 helpers (sm_103a packed-FMA path; ptxas never auto-fuses this)
#define FMA2(d, a, b) \
    asm("fma.rn.f32x2 %0, %1, %2, %3;" : "=l"(d) : "l"(a), "l"(b), "l"(d))
#define PACK2(d, lo, hi) \
    asm("mov.b64 %0, {%1, %2};" : "=l"(d) : "r"(__float_as_uint(lo)), "r"(__float_as_uint(hi)))
#define UNPACK2(lo, hi, s) do { unsigned int _u0, _u1; \
    asm("mov.b64 {%0, %1}, %2;" : "=r"(_u0), "=r"(_u1) : "l"(s)); \
    lo = __uint_as_float(_u0); hi = __uint_as_float(_u1); } while (0)

// Scratch for preprocessed weights: M = W1+W2 (applied to x_j), W2 contiguous.
__device__ float g_M [NN * CC * CC];
__device__ float g_W2[NN * CC * CC];

__global__ void prep_kernel(const float* __restrict__ w) {
    int idx = blockIdx.x * blockDim.x + threadIdx.x;   // over NN*CC*CC
    if (idx >= NN * CC * CC) return;
    int c  = idx & (CC - 1);
    int oi = idx >> 8;                                  // i*CC + o
    const float* row = w + (size_t)oi * (2 * CC);
    float w2 = row[CC + c];
    g_W2[idx] = w2;
    g_M[idx]  = row[c] + w2;
}

// One CTA: fixed i, 64 o-rows, 64 pixels (one b, hw range).
// v_j = M_i @ x_j (j=0..4) and u = W2_i @ x_i, all in packed f32x2 FMA,
// then fused edge/softmax/aggregate epilogue. No intermediates to GMEM.
__global__ __launch_bounds__(256, 1) void fused_kernel(
    const float* __restrict__ x,
    const float* __restrict__ bias,
    float* __restrict__ out)
{
    __shared__ __align__(16) float Ms[KB][TO];          // A tile (k-major: row k, col o)
    __shared__ __align__(16) float Ws[KB][TO];
    __shared__ __align__(16) float Xs[NN][KB][TP];      // B tiles for all 5 x_j

    const int i   = blockIdx.z;
    const int o0  = blockIdx.y * TO;
    const int b   = blockIdx.x >> 4;           // 16 hw-tiles per b
    const int hw0 = (blockIdx.x & 15) * TP;

    const int tid = threadIdx.x;
    const int tx  = tid & 15;                  // pixel sub-tile (2 f32x2 pairs)
    const int ty  = tid >> 4;                  // o sub-tile     (4 rows)

    // Packed accumulators: [j][r][pair]
    unsigned long long accV[NN][4][2];
    unsigned long long accU[4][2];
    #pragma unroll
    for (int j = 0; j < NN; j++)
        #pragma unroll
        for (int r = 0; r < 4; r++) { accV[j][r][0] = 0ULL; accV[j][r][1] = 0ULL; }
    #pragma unroll
    for (int r = 0; r < 4; r++) { accU[r][0] = 0ULL; accU[r][1] = 0ULL; }

    const float* Mi = g_M  + ((size_t)i * CC + o0) * CC;
    const float* Wi = g_W2 + ((size_t)i * CC + o0) * CC;

    // A-tile loader mapping: conflict-free transposed store
    const int lo = tid & 63;                   // o within tile
    const int lk = (tid >> 6) << 2;            // k4 group base (0,4,8,12)

    for (int k0 = 0; k0 < CC; k0 += KB) {
        __syncthreads();
        // --- A tiles: load float4 along k, store transposed [k][o] ---
        {
            const float4 mv = *(const float4*)(Mi + (size_t)lo * CC + k0 + lk);
            Ms[lk + 0][lo] = mv.x; Ms[lk + 1][lo] = mv.y;
            Ms[lk + 2][lo] = mv.z; Ms[lk + 3][lo] = mv.w;
            const float4 wv = *(const float4*)(Wi + (size_t)lo * CC + k0 + lk);
            Ws[lk + 0][lo] = wv.x; Ws[lk + 1][lo] = wv.y;
            Ws[lk + 2][lo] = wv.z; Ws[lk + 3][lo] = wv.w;
        }
        // --- B tiles: 5 * 16k * 16 float4 = 1280 float4; 5 per thread ---
        #pragma unroll
        for (int t = 0; t < 5; t++) {
            int idx = tid + t * 256;
            int p4  = idx & 15;
            int k   = (idx >> 4) & (KB - 1);
            int j   = idx >> 8;
            const float4 xv = *(const float4*)(
                x + ((((size_t)j * BB + b) * CC + k0 + k) * HWD) + hw0 + p4 * 4);
            *(float4*)&Xs[j][k][p4 * 4] = xv;
        }
        __syncthreads();

        // --- 6 simultaneous rank-KB updates, packed f32x2 ---
        #pragma unroll
        for (int k = 0; k < KB; k++) {
            const float4 am4 = *(const float4*)&Ms[k][ty * 4];
            const float4 aw4 = *(const float4*)&Ws[k][ty * 4];
            unsigned long long aM2[4], aW2[4];
            PACK2(aM2[0], am4.x, am4.x); PACK2(aM2[1], am4.y, am4.y);
            PACK2(aM2[2], am4.z, am4.z); PACK2(aM2[3], am4.w, am4.w);
            PACK2(aW2[0], aw4.x, aw4.x); PACK2(aW2[1], aw4.y, aw4.y);
            PACK2(aW2[2], aw4.z, aw4.z); PACK2(aW2[3], aw4.w, aw4.w);

            unsigned long long b2[NN][2];
            #pragma unroll
            for (int j = 0; j < NN; j++) {
                const ulonglong2 q = *(const ulonglong2*)&Xs[j][k][tx * 4];
                b2[j][0] = q.x; b2[j][1] = q.y;
            }
            #pragma unroll
            for (int j = 0; j < NN; j++) {
                #pragma unroll
                for (int r = 0; r < 4; r++) {
                    FMA2(accV[j][r][0], aM2[r], b2[j][0]);
                    FMA2(accV[j][r][1], aM2[r], b2[j][1]);
                }
                if (j == i) {   // u = W2_i @ x_i reuses the x_i B-tile
                    #pragma unroll
                    for (int r = 0; r < 4; r++) {
                        FMA2(accU[r][0], aW2[r], b2[j][0]);
                        FMA2(accU[r][1], aW2[r], b2[j][1]);
                    }
                }
            }
        }
    }

    // --- fused epilogue: t = v_j + u + b; e = |x_j - t| thresholded; softmax_j; sum ---
    #pragma unroll
    for (int r = 0; r < 4; r++) {
        const int o  = o0 + ty * 4 + r;
        const float bv = bias[i * CC + o];
        float xr[NN][4];
        #pragma unroll
        for (int j = 0; j < NN; j++) {
            float4 q = *(const float4*)(
                x + ((((size_t)j * BB + b) * CC + o) * HWD) + hw0 + tx * 4);
            xr[j][0] = q.x; xr[j][1] = q.y; xr[j][2] = q.z; xr[j][3] = q.w;
        }
        float uu[4];
        UNPACK2(uu[0], uu[1], accU[r][0]);
        UNPACK2(uu[2], uu[3], accU[r][1]);
        float vv[NN][4];
        #pragma unroll
        for (int j = 0; j < NN; j++) {
            UNPACK2(vv[j][0], vv[j][1], accV[j][r][0]);
            UNPACK2(vv[j][2], vv[j][3], accV[j][r][1]);
        }
        float resv[4];
        #pragma unroll
        for (int c = 0; c < 4; c++) {
            const float u = uu[c] + bv;
            float e[NN];
            float m = 0.f;                       // all e >= 0, so max >= 0
            #pragma unroll
            for (int j = 0; j < NN; j++) {
                float t = vv[j][c] + u;
                float d = fabsf(xr[j][c] - t);
                e[j] = (d > 0.3f) ? d : 0.f;
                m = fmaxf(m, e[j]);
            }
            float s = 0.f, a = 0.f;
            #pragma unroll
            for (int j = 0; j < NN; j++) {
                float wgt = __expf(e[j] - m);
                s += wgt;
                a = fmaf(wgt, xr[j][c], a);
            }
            resv[c] = a / s;
        }
        *(float4*)(out + ((((size_t)i * BB + b) * CC + o) * HWD) + hw0 + tx * 4) =
            make_float4(resv[0], resv[1], resv[2], resv[3]);
    }
}

extern "C" void kernel_launch(void* const* d_in, const int* in_sizes, int n_in,
                              void* d_out, int out_size) {
    const float* x    = (const float*)d_in[0];   // [5,8,256,32,32]
    const float* w    = (const float*)d_in[1];   // [5,256,512]
    const float* bias = (const float*)d_in[2];   // [5,256]
    float* out = (float*)d_out;                  // [5,8,256,32,32]

    prep_kernel<<<(NN * CC * CC + 255) / 256, 256>>>(w);
    // grid: x = b(8) * hw_tiles(16) = 128, y = o_tiles(4), z = i(5)
    fused_kernel<<<dim3(128, 4, 5), 256>>>(x, bias, out);
}